// round 6
// baseline (speedup 1.0000x reference)
#include <cuda_runtime.h>
#include <math.h>

// ---------------------------------------------------------------------------
// Problem constants
// ---------------------------------------------------------------------------
#define DD 7686
#define HH 512
#define OO 8
#define NN 8206     // DD + HH + OO
#define MM 2048

// ---------------------------------------------------------------------------
// Scratch (device globals: no allocation allowed). 256B-aligned so cp.async
// 16B chunks from these buffers are legal whenever the element offset allows.
// ---------------------------------------------------------------------------
__device__ __align__(256) float g_Q [15740928];        // [2048, 7686]
__device__ __align__(256) float g_Km[15740928];        // [2048, 7686]
__device__ __align__(256) float g_S [4194304];         // [2048, 2048]
__device__ __align__(256) float g_rmax  [2048];
__device__ __align__(256) float g_rscale[2048];
__device__ __align__(256) float g_partW [8 * 2048];
__device__ __align__(256) float g_w     [2048];
__device__ __align__(256) float g_partU [8 * 7686];
__device__ __align__(256) float g_u     [7686];
__device__ __align__(256) float g_partC [16 * 7686];
__device__ __align__(256) float g_ctx   [7686];
__device__ __align__(256) float g_partH [64 * 520];
__device__ __align__(256) float g_h     [520];

// ---------------------------------------------------------------------------
// cp.async helpers
// ---------------------------------------------------------------------------
__device__ __forceinline__ void cp16(unsigned dst, const void* src) {
    asm volatile("cp.async.cg.shared.global [%0], [%1], 16;\n" :: "r"(dst), "l"(src));
}
__device__ __forceinline__ void cp8(unsigned dst, const void* src) {
    asm volatile("cp.async.ca.shared.global [%0], [%1], 8;\n" :: "r"(dst), "l"(src));
}
__device__ __forceinline__ void cp4(unsigned dst, const void* src, int sz) {
    asm volatile("cp.async.ca.shared.global [%0], [%1], 4, %2;\n" :: "r"(dst), "l"(src), "r"(sz));
}
__device__ __forceinline__ void cp16z(unsigned dst, const void* src, int sz) {
    asm volatile("cp.async.cg.shared.global [%0], [%1], 16, %2;\n" :: "r"(dst), "l"(src), "r"(sz));
}
// 16B global->shared load that tolerates 8B-aligned global src.
// Guaranteed safe here: every src offset is an even float index.
__device__ __forceinline__ void ld16_any(unsigned dst, const float* src) {
    if ((((unsigned long long)src) & 15ull) == 0ull) {
        cp16(dst, src);
    } else {
        cp8(dst,     src);
        cp8(dst + 8, src + 2);
    }
}
#define CP_COMMIT()  asm volatile("cp.async.commit_group;\n" ::)
#define CP_WAIT1()   asm volatile("cp.async.wait_group 1;\n" ::)
#define CP_WAIT0()   asm volatile("cp.async.wait_group 0;\n" ::)

// m16n8k8 tf32 MMA (fp32 accum)
__device__ __forceinline__ void mma8(float c[4], const unsigned a[4], const unsigned b[2]) {
    asm volatile(
        "mma.sync.aligned.m16n8k8.row.col.f32.tf32.tf32.f32 "
        "{%0,%1,%2,%3}, {%4,%5,%6,%7}, {%8,%9}, {%0,%1,%2,%3};\n"
        : "+f"(c[0]), "+f"(c[1]), "+f"(c[2]), "+f"(c[3])
        : "r"(a[0]), "r"(a[1]), "r"(a[2]), "r"(a[3]), "r"(b[0]), "r"(b[1]));
}

// ---------------------------------------------------------------------------
// Tiled tf32 GEMM.
//   BT == 0 : C[M,N] = A[M,K] * B[K,N]            (A,B row-major)
//   BT == 1 : C[M,N] = A[M,K] * B[N,K]^T          (both K-contiguous)
// Block tile 128x128, K-tile 16, 8 warps (warp tile 64x32), double-buffered
// cp.async pipeline. Optional per-column bias, scalar scale.
// ---------------------------------------------------------------------------
template <int BT>
__global__ void __launch_bounds__(256, 2)
gemm_tf32(const float* __restrict__ A, const float* __restrict__ B,
          float* __restrict__ C, int Mn, int Nn, int Kn,
          const float* __restrict__ bias, float scale)
{
    constexpr int AS   = 20;                       // A smem row stride (floats)
    constexpr int BS   = BT ? 20 : 136;            // B smem row stride
    constexpr int AELE = 128 * AS;
    constexpr int BELE = BT ? (128 * 20) : (16 * 136);

    __shared__ float As[2][AELE];
    __shared__ float Bs[2][BELE];

    const int t    = threadIdx.x;
    const int warp = t >> 5, lane = t & 31;
    const int grp  = lane >> 2, tig = lane & 3;
    const int wm   = warp & 1, wn = warp >> 1;
    const int bM   = blockIdx.x, bN = blockIdx.y;

    const unsigned sA = (unsigned)__cvta_generic_to_shared(&As[0][0]);
    const unsigned sB = (unsigned)__cvta_generic_to_shared(&Bs[0][0]);

    float acc[4][4][4];
#pragma unroll
    for (int i = 0; i < 4; i++)
#pragma unroll
        for (int j = 0; j < 4; j++)
#pragma unroll
            for (int k = 0; k < 4; k++) acc[i][j][k] = 0.f;

    const int nK = (Kn + 15) >> 4;

    auto loadTile = [&](int buf, int k0) {
        // ---- A tile: 128 rows x 16 floats = 512 16B chunks ----
#pragma unroll
        for (int i = 0; i < 2; i++) {
            int c = t + 256 * i;
            int row = c >> 2, kc = (c & 3) << 2;
            int gk = k0 + kc;
            size_t goff = (size_t)(bM * 128 + row) * Kn + gk;
            unsigned dst = sA + (unsigned)(buf * AELE + row * AS + kc) * 4u;
            if (gk + 4 <= Kn) {
                ld16_any(dst, A + goff);
            } else {
#pragma unroll
                for (int e = 0; e < 4; e++) {
                    bool v = (gk + e) < Kn;
                    cp4(dst + 4 * e, v ? (A + goff + e) : A, v ? 4 : 0);
                }
            }
        }
        // ---- B tile ----
#pragma unroll
        for (int i = 0; i < 2; i++) {
            int c = t + 256 * i;
            if (BT == 0) {
                int row = c >> 5, nc = (c & 31) << 2;       // row = k index
                int gk = k0 + row;
                int gn = bN * 128 + nc;
                unsigned dst = sB + (unsigned)(buf * BELE + row * BS + nc) * 4u;
                if (gk < Kn) {
                    size_t goff = (size_t)gk * Nn + gn;
                    if (gn + 4 <= Nn) {
                        ld16_any(dst, B + goff);
                    } else {
#pragma unroll
                        for (int e = 0; e < 4; e++) {
                            bool v = (gn + e) < Nn;
                            cp4(dst + 4 * e, v ? (B + goff + e) : B, v ? 4 : 0);
                        }
                    }
                } else {
                    cp16z(dst, B, 0);
                }
            } else {
                int row = c >> 2, kc = (c & 3) << 2;        // row = n index
                int gn = bN * 128 + row;
                int gk = k0 + kc;
                unsigned dst = sB + (unsigned)(buf * BELE + row * BS + kc) * 4u;
                if (gn < Nn) {
                    size_t goff = (size_t)gn * Kn + gk;
                    if (gk + 4 <= Kn) {
                        ld16_any(dst, B + goff);
                    } else {
#pragma unroll
                        for (int e = 0; e < 4; e++) {
                            bool v = (gk + e) < Kn;
                            cp4(dst + 4 * e, v ? (B + goff + e) : B, v ? 4 : 0);
                        }
                    }
                } else {
                    cp16z(dst, B, 0);
                }
            }
        }
    };

    loadTile(0, 0);
    CP_COMMIT();

    for (int kt = 0; kt < nK; kt++) {
        if (kt + 1 < nK) {
            loadTile((kt + 1) & 1, (kt + 1) << 4);
            CP_COMMIT();
            CP_WAIT1();
        } else {
            CP_WAIT0();
        }
        __syncthreads();

        const float* Ab = As[kt & 1];
        const float* Bb = Bs[kt & 1];

#pragma unroll
        for (int s = 0; s < 2; s++) {
            const int kb = s << 3;
            unsigned a[4][4], b[4][2];
#pragma unroll
            for (int im = 0; im < 4; im++) {
                int r = wm * 64 + im * 16 + grp;
                a[im][0] = __float_as_uint(Ab[r * AS + kb + tig]);
                a[im][1] = __float_as_uint(Ab[(r + 8) * AS + kb + tig]);
                a[im][2] = __float_as_uint(Ab[r * AS + kb + tig + 4]);
                a[im][3] = __float_as_uint(Ab[(r + 8) * AS + kb + tig + 4]);
            }
#pragma unroll
            for (int jn = 0; jn < 4; jn++) {
                int cc = wn * 32 + jn * 8 + grp;
                if (BT == 0) {
                    b[jn][0] = __float_as_uint(Bb[(kb + tig) * BS + cc]);
                    b[jn][1] = __float_as_uint(Bb[(kb + tig + 4) * BS + cc]);
                } else {
                    b[jn][0] = __float_as_uint(Bb[cc * BS + kb + tig]);
                    b[jn][1] = __float_as_uint(Bb[cc * BS + kb + tig + 4]);
                }
            }
#pragma unroll
            for (int im = 0; im < 4; im++)
#pragma unroll
                for (int jn = 0; jn < 4; jn++)
                    mma8(acc[im][jn], a[im], b[jn]);
        }
        __syncthreads();
    }

    // ---- epilogue ----
#pragma unroll
    for (int im = 0; im < 4; im++) {
#pragma unroll
        for (int jn = 0; jn < 4; jn++) {
            int r  = bM * 128 + wm * 64 + im * 16 + grp;
            int cc = bN * 128 + wn * 32 + jn * 8 + (tig << 1);
            if (r >= Mn) continue;
            size_t o = (size_t)r * Nn + cc;
            if (cc < Nn) {
                float bb = bias ? bias[cc] : 0.f;
                C[o]                    = acc[im][jn][0] * scale + bb;
                C[o + (size_t)8 * Nn]   = acc[im][jn][2] * scale + bb;
            }
            if (cc + 1 < Nn) {
                float bb = bias ? bias[cc + 1] : 0.f;
                C[o + 1]                  = acc[im][jn][1] * scale + bb;
                C[o + 1 + (size_t)8 * Nn] = acc[im][jn][3] * scale + bb;
            }
        }
    }
}

// ---------------------------------------------------------------------------
// Softmax row stats: per-row max and 1/(M*Z)
// ---------------------------------------------------------------------------
__global__ void row_softmax_stats(const float* __restrict__ S,
                                  float* __restrict__ rmax, float* __restrict__ rscale)
{
    __shared__ float red[256];
    const int m = blockIdx.x, t = threadIdx.x;
    const float* row = S + (size_t)m * MM;

    float mx = -3.402823e38f;
    for (int j = t; j < MM; j += 256) mx = fmaxf(mx, row[j]);
    red[t] = mx; __syncthreads();
    for (int s = 128; s > 0; s >>= 1) { if (t < s) red[t] = fmaxf(red[t], red[t + s]); __syncthreads(); }
    mx = red[0]; __syncthreads();

    float sm = 0.f;
    for (int j = t; j < MM; j += 256) sm += __expf(row[j] - mx);
    red[t] = sm; __syncthreads();
    for (int s = 128; s > 0; s >>= 1) { if (t < s) red[t] += red[t + s]; __syncthreads(); }
    if (t == 0) { rmax[m] = mx; rscale[m] = 1.f / (red[0] * (float)MM); }
}

// Column mean of softmax(S): partial over m-chunks of 256, then reduce.
__global__ void colmean_partial(const float* __restrict__ S,
                                const float* __restrict__ rmax,
                                const float* __restrict__ rscale,
                                float* __restrict__ part)
{
    const int j  = blockIdx.x * 256 + threadIdx.x;   // < 2048
    const int mb = blockIdx.y;
    const int m0 = mb * 256;
    float acc = 0.f;
#pragma unroll 4
    for (int m = m0; m < m0 + 256; m++)
        acc += __expf(S[(size_t)m * MM + j] - rmax[m]) * rscale[m];
    part[mb * MM + j] = acc;
}

__global__ void reduce_w(const float* __restrict__ part, float* __restrict__ w)
{
    const int j = blockIdx.x * 256 + threadIdx.x;
    float s = 0.f;
#pragma unroll
    for (int c = 0; c < 8; c++) s += part[c * MM + j];
    w[j] = s;
}

// u = w^T X  : partial over m-chunks
__global__ void wx_partial(const float* __restrict__ X, const float* __restrict__ w,
                           float* __restrict__ part)
{
    const int d  = blockIdx.x * 256 + threadIdx.x;
    const int mb = blockIdx.y;
    if (d >= DD) return;
    const int m0 = mb * 256;
    float acc = 0.f;
#pragma unroll 4
    for (int m = m0; m < m0 + 256; m++)
        acc += w[m] * X[(size_t)m * DD + d];
    part[mb * DD + d] = acc;
}

__global__ void reduce_u(const float* __restrict__ part, float* __restrict__ u)
{
    const int d = blockIdx.x * 256 + threadIdx.x;
    if (d >= DD) return;
    float s = 0.f;
#pragma unroll
    for (int c = 0; c < 8; c++) s += part[c * DD + d];
    u[d] = s;
}

// context = u @ Wv + bv : partial over k-chunks of 481
__global__ void uwv_partial(const float* __restrict__ u, const float* __restrict__ Wv,
                            float* __restrict__ part)
{
    const int n  = blockIdx.x * 256 + threadIdx.x;
    const int kb = blockIdx.y;
    if (n >= DD) return;
    const int k0 = kb * 481;
    const int k1 = (k0 + 481 < DD) ? (k0 + 481) : DD;
    float acc = 0.f;
    for (int k = k0; k < k1; k++)
        acc += u[k] * Wv[(size_t)k * DD + n];
    part[kb * DD + n] = acc;
}

__global__ void reduce_ctx(const float* __restrict__ part, const float* __restrict__ bv,
                           float* __restrict__ ctx)
{
    const int n = blockIdx.x * 256 + threadIdx.x;
    if (n >= DD) return;
    float s = 0.f;
#pragma unroll
    for (int c = 0; c < 16; c++) s += part[c * DD + n];
    ctx[n] = s + bv[n];
}

// Sweep 1: h_j = tanh( sum_{i<D} ctx_i * W[i, D+j] + b[D+j] ), j in [0, 520)
__global__ void sweep1_partial(const float* __restrict__ ctx,
                               const float* __restrict__ mu,
                               const float* __restrict__ sg,
                               const float* __restrict__ ep,
                               float* __restrict__ part)
{
    const int j  = blockIdx.x * 256 + threadIdx.x;
    const int ib = blockIdx.y;
    if (j >= HH + OO) return;
    const int i0 = ib * 121;
    const int i1 = (i0 + 121 < DD) ? (i0 + 121) : DD;
    float acc = 0.f;
    for (int i = i0; i < i1; i++) {
        size_t off = (size_t)i * NN + DD + j;
        acc += ctx[i] * (mu[off] + sg[off] * ep[off]);
    }
    part[ib * (HH + OO) + j] = acc;
}

__global__ void reduce_h(const float* __restrict__ part,
                         const float* __restrict__ bmu, const float* __restrict__ bsg,
                         const float* __restrict__ epb, float* __restrict__ h)
{
    const int j = blockIdx.x * 256 + threadIdx.x;
    if (j >= HH + OO) return;
    float s = 0.f;
#pragma unroll
    for (int c = 0; c < 64; c++) s += part[c * (HH + OO) + j];
    s += bmu[DD + j] + bsg[DD + j] * epb[DD + j];
    h[j] = tanhf(s);
}

// Sweep 2: out_o = sigmoid( tanh( sum_i z_i * W[i, D+H+o] + b[D+H+o] ) ),
// z = [context ; h], only the last 8 columns of W needed.
__global__ void sweep2_out(const float* __restrict__ ctx, const float* __restrict__ h,
                           const float* __restrict__ mu, const float* __restrict__ sg,
                           const float* __restrict__ ep,
                           const float* __restrict__ bmu, const float* __restrict__ bsg,
                           const float* __restrict__ epb, float* __restrict__ out)
{
    __shared__ float red[8][256];
    const int t = threadIdx.x;
    float acc[8];
#pragma unroll
    for (int o = 0; o < 8; o++) acc[o] = 0.f;

    for (int i = t; i < NN; i += 256) {
        float zi = (i < DD) ? ctx[i] : h[i - DD];
        size_t base = (size_t)i * NN + (DD + HH);
#pragma unroll
        for (int o = 0; o < 8; o++)
            acc[o] += zi * (mu[base + o] + sg[base + o] * ep[base + o]);
    }
#pragma unroll
    for (int o = 0; o < 8; o++) red[o][t] = acc[o];
    __syncthreads();
    for (int s = 128; s > 0; s >>= 1) {
        if (t < s) {
#pragma unroll
            for (int o = 0; o < 8; o++) red[o][t] += red[o][t + s];
        }
        __syncthreads();
    }
    if (t < 8) {
        float b2 = bmu[DD + HH + t] + bsg[DD + HH + t] * epb[DD + HH + t];
        float v  = tanhf(red[t][0] + b2);
        out[t] = 1.f / (1.f + expf(-v));
    }
}

// ---------------------------------------------------------------------------
// Launch
// ---------------------------------------------------------------------------
extern "C" void kernel_launch(void* const* d_in, const int* in_sizes, int n_in,
                              void* d_out, int out_size)
{
    const float* X   = (const float*)d_in[0];
    const float* Wq  = (const float*)d_in[1];
    const float* bq  = (const float*)d_in[2];
    const float* Wk  = (const float*)d_in[3];
    const float* bk  = (const float*)d_in[4];
    const float* Wv  = (const float*)d_in[5];
    const float* bv  = (const float*)d_in[6];
    const float* mu  = (const float*)d_in[7];
    const float* sg  = (const float*)d_in[8];
    const float* bmu = (const float*)d_in[9];
    const float* bsg = (const float*)d_in[10];
    const float* epw = (const float*)d_in[11];
    const float* epb = (const float*)d_in[12];
    float* out = (float*)d_out;

    float *Q, *Km, *S, *rmax, *rscale, *partW, *w, *partU, *u, *partC, *ctx, *partH, *h;
    cudaGetSymbolAddress((void**)&Q,      g_Q);
    cudaGetSymbolAddress((void**)&Km,     g_Km);
    cudaGetSymbolAddress((void**)&S,      g_S);
    cudaGetSymbolAddress((void**)&rmax,   g_rmax);
    cudaGetSymbolAddress((void**)&rscale, g_rscale);
    cudaGetSymbolAddress((void**)&partW,  g_partW);
    cudaGetSymbolAddress((void**)&w,      g_w);
    cudaGetSymbolAddress((void**)&partU,  g_partU);
    cudaGetSymbolAddress((void**)&u,      g_u);
    cudaGetSymbolAddress((void**)&partC,  g_partC);
    cudaGetSymbolAddress((void**)&ctx,    g_ctx);
    cudaGetSymbolAddress((void**)&partH,  g_partH);
    cudaGetSymbolAddress((void**)&h,      g_h);

    const float inv_sqrt_d = 1.0f / sqrtf((float)DD);

    // Q = X Wq + bq ; K = X Wk + bk   (grid x = m fastest for B-column L2 reuse)
    gemm_tf32<0><<<dim3(16, 61), 256>>>(X, Wq, Q,  MM, DD, DD, bq, 1.0f);
    gemm_tf32<0><<<dim3(16, 61), 256>>>(X, Wk, Km, MM, DD, DD, bk, 1.0f);
    // S = Q K^T / sqrt(D)
    gemm_tf32<1><<<dim3(16, 16), 256>>>(Q, Km, S, MM, MM, DD, nullptr, inv_sqrt_d);

    // softmax column mean -> w
    row_softmax_stats<<<MM, 256>>>(S, rmax, rscale);
    colmean_partial<<<dim3(8, 8), 256>>>(S, rmax, rscale, partW);
    reduce_w<<<8, 256>>>(partW, w);

    // u = w^T X
    wx_partial<<<dim3(31, 8), 256>>>(X, w, partU);
    reduce_u<<<31, 256>>>(partU, u);

    // context = u Wv + bv
    uwv_partial<<<dim3(31, 16), 256>>>(u, Wv, partC);
    reduce_ctx<<<31, 256>>>(partC, bv, ctx);

    // sweep 1 (520 hidden+output nodes)
    sweep1_partial<<<dim3(3, 64), 256>>>(ctx, mu, sg, epw, partH);
    reduce_h<<<3, 256>>>(partH, bmu, bsg, epb, h);

    // sweep 2 (final 8 outputs)
    sweep2_out<<<1, 256>>>(ctx, h, mu, sg, epw, bmu, bsg, epb, out);
}

// round 7
// speedup vs baseline: 1.0001x; 1.0001x over previous
#include <cuda_runtime.h>
#include <math.h>

// ---------------------------------------------------------------------------
// Problem constants
// ---------------------------------------------------------------------------
#define DD 7686
#define HH 512
#define OO 8
#define NN 8206     // DD + HH + OO
#define MM 2048

// ---------------------------------------------------------------------------
// Scratch (device globals: no allocation allowed). 256B-aligned so cp.async
// 16B chunks from these buffers are legal whenever the element offset allows.
// ---------------------------------------------------------------------------
__device__ __align__(256) float g_Q [15740928];        // [2048, 7686]
__device__ __align__(256) float g_Km[15740928];        // [2048, 7686]
__device__ __align__(256) float g_S [4194304];         // [2048, 2048]
__device__ __align__(256) float g_rmax  [2048];
__device__ __align__(256) float g_rscale[2048];
__device__ __align__(256) float g_partW [8 * 2048];
__device__ __align__(256) float g_w     [2048];
__device__ __align__(256) float g_partU [8 * 7686];
__device__ __align__(256) float g_u     [7686];
__device__ __align__(256) float g_partC [16 * 7686];
__device__ __align__(256) float g_ctx   [7686];
__device__ __align__(256) float g_partH [64 * 520];
__device__ __align__(256) float g_h     [520];

// ---------------------------------------------------------------------------
// cp.async helpers
// ---------------------------------------------------------------------------
__device__ __forceinline__ void cp16(unsigned dst, const void* src) {
    asm volatile("cp.async.cg.shared.global [%0], [%1], 16;\n" :: "r"(dst), "l"(src));
}
__device__ __forceinline__ void cp8(unsigned dst, const void* src) {
    asm volatile("cp.async.ca.shared.global [%0], [%1], 8;\n" :: "r"(dst), "l"(src));
}
__device__ __forceinline__ void cp4(unsigned dst, const void* src, int sz) {
    asm volatile("cp.async.ca.shared.global [%0], [%1], 4, %2;\n" :: "r"(dst), "l"(src), "r"(sz));
}
__device__ __forceinline__ void cp16z(unsigned dst, const void* src, int sz) {
    asm volatile("cp.async.cg.shared.global [%0], [%1], 16, %2;\n" :: "r"(dst), "l"(src), "r"(sz));
}
// 16B global->shared load that tolerates 8B-aligned global src.
// Guaranteed safe here: every src offset is an even float index.
__device__ __forceinline__ void ld16_any(unsigned dst, const float* src) {
    if ((((unsigned long long)src) & 15ull) == 0ull) {
        cp16(dst, src);
    } else {
        cp8(dst,     src);
        cp8(dst + 8, src + 2);
    }
}
#define CP_COMMIT()  asm volatile("cp.async.commit_group;\n" ::)
#define CP_WAIT1()   asm volatile("cp.async.wait_group 1;\n" ::)
#define CP_WAIT0()   asm volatile("cp.async.wait_group 0;\n" ::)

// m16n8k8 tf32 MMA (fp32 accum)
__device__ __forceinline__ void mma8(float c[4], const unsigned a[4], const unsigned b[2]) {
    asm volatile(
        "mma.sync.aligned.m16n8k8.row.col.f32.tf32.tf32.f32 "
        "{%0,%1,%2,%3}, {%4,%5,%6,%7}, {%8,%9}, {%0,%1,%2,%3};\n"
        : "+f"(c[0]), "+f"(c[1]), "+f"(c[2]), "+f"(c[3])
        : "r"(a[0]), "r"(a[1]), "r"(a[2]), "r"(a[3]), "r"(b[0]), "r"(b[1]));
}

// ---------------------------------------------------------------------------
// Tiled tf32 GEMM.
//   BT == 0 : C[M,N] = A[M,K] * B[K,N]            (A,B row-major)
//   BT == 1 : C[M,N] = A[M,K] * B[N,K]^T          (both K-contiguous)
// Block tile 128x128, K-tile 16, 8 warps (warp tile 64x32), double-buffered
// cp.async pipeline. Optional per-column bias, scalar scale.
// ---------------------------------------------------------------------------
template <int BT>
__global__ void __launch_bounds__(256, 2)
gemm_tf32(const float* __restrict__ A, const float* __restrict__ B,
          float* __restrict__ C, int Mn, int Nn, int Kn,
          const float* __restrict__ bias, float scale)
{
    constexpr int AS   = 20;                       // A smem row stride (floats)
    constexpr int BS   = BT ? 20 : 136;            // B smem row stride
    constexpr int AELE = 128 * AS;
    constexpr int BELE = BT ? (128 * 20) : (16 * 136);

    __shared__ float As[2][AELE];
    __shared__ float Bs[2][BELE];

    const int t    = threadIdx.x;
    const int warp = t >> 5, lane = t & 31;
    const int grp  = lane >> 2, tig = lane & 3;
    const int wm   = warp & 1, wn = warp >> 1;
    const int bM   = blockIdx.x, bN = blockIdx.y;

    const unsigned sA = (unsigned)__cvta_generic_to_shared(&As[0][0]);
    const unsigned sB = (unsigned)__cvta_generic_to_shared(&Bs[0][0]);

    float acc[4][4][4];
#pragma unroll
    for (int i = 0; i < 4; i++)
#pragma unroll
        for (int j = 0; j < 4; j++)
#pragma unroll
            for (int k = 0; k < 4; k++) acc[i][j][k] = 0.f;

    const int nK = (Kn + 15) >> 4;

    auto loadTile = [&](int buf, int k0) {
        // ---- A tile: 128 rows x 16 floats = 512 16B chunks ----
#pragma unroll
        for (int i = 0; i < 2; i++) {
            int c = t + 256 * i;
            int row = c >> 2, kc = (c & 3) << 2;
            int gk = k0 + kc;
            size_t goff = (size_t)(bM * 128 + row) * Kn + gk;
            unsigned dst = sA + (unsigned)(buf * AELE + row * AS + kc) * 4u;
            if (gk + 4 <= Kn) {
                ld16_any(dst, A + goff);
            } else {
#pragma unroll
                for (int e = 0; e < 4; e++) {
                    bool v = (gk + e) < Kn;
                    cp4(dst + 4 * e, v ? (A + goff + e) : A, v ? 4 : 0);
                }
            }
        }
        // ---- B tile ----
#pragma unroll
        for (int i = 0; i < 2; i++) {
            int c = t + 256 * i;
            if (BT == 0) {
                int row = c >> 5, nc = (c & 31) << 2;       // row = k index
                int gk = k0 + row;
                int gn = bN * 128 + nc;
                unsigned dst = sB + (unsigned)(buf * BELE + row * BS + nc) * 4u;
                if (gk < Kn) {
                    size_t goff = (size_t)gk * Nn + gn;
                    if (gn + 4 <= Nn) {
                        ld16_any(dst, B + goff);
                    } else {
#pragma unroll
                        for (int e = 0; e < 4; e++) {
                            bool v = (gn + e) < Nn;
                            cp4(dst + 4 * e, v ? (B + goff + e) : B, v ? 4 : 0);
                        }
                    }
                } else {
                    cp16z(dst, B, 0);
                }
            } else {
                int row = c >> 2, kc = (c & 3) << 2;        // row = n index
                int gn = bN * 128 + row;
                int gk = k0 + kc;
                unsigned dst = sB + (unsigned)(buf * BELE + row * BS + kc) * 4u;
                if (gn < Nn) {
                    size_t goff = (size_t)gn * Kn + gk;
                    if (gk + 4 <= Kn) {
                        ld16_any(dst, B + goff);
                    } else {
#pragma unroll
                        for (int e = 0; e < 4; e++) {
                            bool v = (gk + e) < Kn;
                            cp4(dst + 4 * e, v ? (B + goff + e) : B, v ? 4 : 0);
                        }
                    }
                } else {
                    cp16z(dst, B, 0);
                }
            }
        }
    };

    loadTile(0, 0);
    CP_COMMIT();

    for (int kt = 0; kt < nK; kt++) {
        if (kt + 1 < nK) {
            loadTile((kt + 1) & 1, (kt + 1) << 4);
            CP_COMMIT();
            CP_WAIT1();
        } else {
            CP_WAIT0();
        }
        __syncthreads();

        const float* Ab = As[kt & 1];
        const float* Bb = Bs[kt & 1];

#pragma unroll
        for (int s = 0; s < 2; s++) {
            const int kb = s << 3;
            unsigned a[4][4], b[4][2];
#pragma unroll
            for (int im = 0; im < 4; im++) {
                int r = wm * 64 + im * 16 + grp;
                a[im][0] = __float_as_uint(Ab[r * AS + kb + tig]);
                a[im][1] = __float_as_uint(Ab[(r + 8) * AS + kb + tig]);
                a[im][2] = __float_as_uint(Ab[r * AS + kb + tig + 4]);
                a[im][3] = __float_as_uint(Ab[(r + 8) * AS + kb + tig + 4]);
            }
#pragma unroll
            for (int jn = 0; jn < 4; jn++) {
                int cc = wn * 32 + jn * 8 + grp;
                if (BT == 0) {
                    b[jn][0] = __float_as_uint(Bb[(kb + tig) * BS + cc]);
                    b[jn][1] = __float_as_uint(Bb[(kb + tig + 4) * BS + cc]);
                } else {
                    b[jn][0] = __float_as_uint(Bb[cc * BS + kb + tig]);
                    b[jn][1] = __float_as_uint(Bb[cc * BS + kb + tig + 4]);
                }
            }
#pragma unroll
            for (int im = 0; im < 4; im++)
#pragma unroll
                for (int jn = 0; jn < 4; jn++)
                    mma8(acc[im][jn], a[im], b[jn]);
        }
        __syncthreads();
    }

    // ---- epilogue ----
#pragma unroll
    for (int im = 0; im < 4; im++) {
#pragma unroll
        for (int jn = 0; jn < 4; jn++) {
            int r  = bM * 128 + wm * 64 + im * 16 + grp;
            int cc = bN * 128 + wn * 32 + jn * 8 + (tig << 1);
            if (r >= Mn) continue;
            size_t o = (size_t)r * Nn + cc;
            if (cc < Nn) {
                float bb = bias ? bias[cc] : 0.f;
                C[o]                    = acc[im][jn][0] * scale + bb;
                C[o + (size_t)8 * Nn]   = acc[im][jn][2] * scale + bb;
            }
            if (cc + 1 < Nn) {
                float bb = bias ? bias[cc + 1] : 0.f;
                C[o + 1]                  = acc[im][jn][1] * scale + bb;
                C[o + 1 + (size_t)8 * Nn] = acc[im][jn][3] * scale + bb;
            }
        }
    }
}

// ---------------------------------------------------------------------------
// Softmax row stats: per-row max and 1/(M*Z)
// ---------------------------------------------------------------------------
__global__ void row_softmax_stats(const float* __restrict__ S,
                                  float* __restrict__ rmax, float* __restrict__ rscale)
{
    __shared__ float red[256];
    const int m = blockIdx.x, t = threadIdx.x;
    const float* row = S + (size_t)m * MM;

    float mx = -3.402823e38f;
    for (int j = t; j < MM; j += 256) mx = fmaxf(mx, row[j]);
    red[t] = mx; __syncthreads();
    for (int s = 128; s > 0; s >>= 1) { if (t < s) red[t] = fmaxf(red[t], red[t + s]); __syncthreads(); }
    mx = red[0]; __syncthreads();

    float sm = 0.f;
    for (int j = t; j < MM; j += 256) sm += __expf(row[j] - mx);
    red[t] = sm; __syncthreads();
    for (int s = 128; s > 0; s >>= 1) { if (t < s) red[t] += red[t + s]; __syncthreads(); }
    if (t == 0) { rmax[m] = mx; rscale[m] = 1.f / (red[0] * (float)MM); }
}

// Column mean of softmax(S): partial over m-chunks of 256, then reduce.
__global__ void colmean_partial(const float* __restrict__ S,
                                const float* __restrict__ rmax,
                                const float* __restrict__ rscale,
                                float* __restrict__ part)
{
    const int j  = blockIdx.x * 256 + threadIdx.x;   // < 2048
    const int mb = blockIdx.y;
    const int m0 = mb * 256;
    float acc = 0.f;
#pragma unroll 4
    for (int m = m0; m < m0 + 256; m++)
        acc += __expf(S[(size_t)m * MM + j] - rmax[m]) * rscale[m];
    part[mb * MM + j] = acc;
}

__global__ void reduce_w(const float* __restrict__ part, float* __restrict__ w)
{
    const int j = blockIdx.x * 256 + threadIdx.x;
    float s = 0.f;
#pragma unroll
    for (int c = 0; c < 8; c++) s += part[c * MM + j];
    w[j] = s;
}

// u = w^T X  : partial over m-chunks
__global__ void wx_partial(const float* __restrict__ X, const float* __restrict__ w,
                           float* __restrict__ part)
{
    const int d  = blockIdx.x * 256 + threadIdx.x;
    const int mb = blockIdx.y;
    if (d >= DD) return;
    const int m0 = mb * 256;
    float acc = 0.f;
#pragma unroll 4
    for (int m = m0; m < m0 + 256; m++)
        acc += w[m] * X[(size_t)m * DD + d];
    part[mb * DD + d] = acc;
}

__global__ void reduce_u(const float* __restrict__ part, float* __restrict__ u)
{
    const int d = blockIdx.x * 256 + threadIdx.x;
    if (d >= DD) return;
    float s = 0.f;
#pragma unroll
    for (int c = 0; c < 8; c++) s += part[c * DD + d];
    u[d] = s;
}

// context = u @ Wv + bv : partial over k-chunks of 481
__global__ void uwv_partial(const float* __restrict__ u, const float* __restrict__ Wv,
                            float* __restrict__ part)
{
    const int n  = blockIdx.x * 256 + threadIdx.x;
    const int kb = blockIdx.y;
    if (n >= DD) return;
    const int k0 = kb * 481;
    const int k1 = (k0 + 481 < DD) ? (k0 + 481) : DD;
    float acc = 0.f;
    for (int k = k0; k < k1; k++)
        acc += u[k] * Wv[(size_t)k * DD + n];
    part[kb * DD + n] = acc;
}

__global__ void reduce_ctx(const float* __restrict__ part, const float* __restrict__ bv,
                           float* __restrict__ ctx)
{
    const int n = blockIdx.x * 256 + threadIdx.x;
    if (n >= DD) return;
    float s = 0.f;
#pragma unroll
    for (int c = 0; c < 16; c++) s += part[c * DD + n];
    ctx[n] = s + bv[n];
}

// Sweep 1: h_j = tanh( sum_{i<D} ctx_i * W[i, D+j] + b[D+j] ), j in [0, 520)
__global__ void sweep1_partial(const float* __restrict__ ctx,
                               const float* __restrict__ mu,
                               const float* __restrict__ sg,
                               const float* __restrict__ ep,
                               float* __restrict__ part)
{
    const int j  = blockIdx.x * 256 + threadIdx.x;
    const int ib = blockIdx.y;
    if (j >= HH + OO) return;
    const int i0 = ib * 121;
    const int i1 = (i0 + 121 < DD) ? (i0 + 121) : DD;
    float acc = 0.f;
    for (int i = i0; i < i1; i++) {
        size_t off = (size_t)i * NN + DD + j;
        acc += ctx[i] * (mu[off] + sg[off] * ep[off]);
    }
    part[ib * (HH + OO) + j] = acc;
}

__global__ void reduce_h(const float* __restrict__ part,
                         const float* __restrict__ bmu, const float* __restrict__ bsg,
                         const float* __restrict__ epb, float* __restrict__ h)
{
    const int j = blockIdx.x * 256 + threadIdx.x;
    if (j >= HH + OO) return;
    float s = 0.f;
#pragma unroll
    for (int c = 0; c < 64; c++) s += part[c * (HH + OO) + j];
    s += bmu[DD + j] + bsg[DD + j] * epb[DD + j];
    h[j] = tanhf(s);
}

// Sweep 2: out_o = sigmoid( tanh( sum_i z_i * W[i, D+H+o] + b[D+H+o] ) ),
// z = [context ; h], only the last 8 columns of W needed.
__global__ void sweep2_out(const float* __restrict__ ctx, const float* __restrict__ h,
                           const float* __restrict__ mu, const float* __restrict__ sg,
                           const float* __restrict__ ep,
                           const float* __restrict__ bmu, const float* __restrict__ bsg,
                           const float* __restrict__ epb, float* __restrict__ out)
{
    __shared__ float red[8][256];
    const int t = threadIdx.x;
    float acc[8];
#pragma unroll
    for (int o = 0; o < 8; o++) acc[o] = 0.f;

    for (int i = t; i < NN; i += 256) {
        float zi = (i < DD) ? ctx[i] : h[i - DD];
        size_t base = (size_t)i * NN + (DD + HH);
#pragma unroll
        for (int o = 0; o < 8; o++)
            acc[o] += zi * (mu[base + o] + sg[base + o] * ep[base + o]);
    }
#pragma unroll
    for (int o = 0; o < 8; o++) red[o][t] = acc[o];
    __syncthreads();
    for (int s = 128; s > 0; s >>= 1) {
        if (t < s) {
#pragma unroll
            for (int o = 0; o < 8; o++) red[o][t] += red[o][t + s];
        }
        __syncthreads();
    }
    if (t < 8) {
        float b2 = bmu[DD + HH + t] + bsg[DD + HH + t] * epb[DD + HH + t];
        float v  = tanhf(red[t][0] + b2);
        out[t] = 1.f / (1.f + expf(-v));
    }
}

// ---------------------------------------------------------------------------
// Launch
// ---------------------------------------------------------------------------
extern "C" void kernel_launch(void* const* d_in, const int* in_sizes, int n_in,
                              void* d_out, int out_size)
{
    const float* X   = (const float*)d_in[0];
    const float* Wq  = (const float*)d_in[1];
    const float* bq  = (const float*)d_in[2];
    const float* Wk  = (const float*)d_in[3];
    const float* bk  = (const float*)d_in[4];
    const float* Wv  = (const float*)d_in[5];
    const float* bv  = (const float*)d_in[6];
    const float* mu  = (const float*)d_in[7];
    const float* sg  = (const float*)d_in[8];
    const float* bmu = (const float*)d_in[9];
    const float* bsg = (const float*)d_in[10];
    const float* epw = (const float*)d_in[11];
    const float* epb = (const float*)d_in[12];
    float* out = (float*)d_out;

    float *Q, *Km, *S, *rmax, *rscale, *partW, *w, *partU, *u, *partC, *ctx, *partH, *h;
    cudaGetSymbolAddress((void**)&Q,      g_Q);
    cudaGetSymbolAddress((void**)&Km,     g_Km);
    cudaGetSymbolAddress((void**)&S,      g_S);
    cudaGetSymbolAddress((void**)&rmax,   g_rmax);
    cudaGetSymbolAddress((void**)&rscale, g_rscale);
    cudaGetSymbolAddress((void**)&partW,  g_partW);
    cudaGetSymbolAddress((void**)&w,      g_w);
    cudaGetSymbolAddress((void**)&partU,  g_partU);
    cudaGetSymbolAddress((void**)&u,      g_u);
    cudaGetSymbolAddress((void**)&partC,  g_partC);
    cudaGetSymbolAddress((void**)&ctx,    g_ctx);
    cudaGetSymbolAddress((void**)&partH,  g_partH);
    cudaGetSymbolAddress((void**)&h,      g_h);

    const float inv_sqrt_d = 1.0f / sqrtf((float)DD);

    // Q = X Wq + bq ; K = X Wk + bk   (grid x = m fastest for B-column L2 reuse)
    gemm_tf32<0><<<dim3(16, 61), 256>>>(X, Wq, Q,  MM, DD, DD, bq, 1.0f);
    gemm_tf32<0><<<dim3(16, 61), 256>>>(X, Wk, Km, MM, DD, DD, bk, 1.0f);
    // S = Q K^T / sqrt(D)
    gemm_tf32<1><<<dim3(16, 16), 256>>>(Q, Km, S, MM, MM, DD, nullptr, inv_sqrt_d);

    // softmax column mean -> w
    row_softmax_stats<<<MM, 256>>>(S, rmax, rscale);
    colmean_partial<<<dim3(8, 8), 256>>>(S, rmax, rscale, partW);
    reduce_w<<<8, 256>>>(partW, w);

    // u = w^T X
    wx_partial<<<dim3(31, 8), 256>>>(X, w, partU);
    reduce_u<<<31, 256>>>(partU, u);

    // context = u Wv + bv
    uwv_partial<<<dim3(31, 16), 256>>>(u, Wv, partC);
    reduce_ctx<<<31, 256>>>(partC, bv, ctx);

    // sweep 1 (520 hidden+output nodes)
    sweep1_partial<<<dim3(3, 64), 256>>>(ctx, mu, sg, epw, partH);
    reduce_h<<<3, 256>>>(partH, bmu, bsg, epb, h);

    // sweep 2 (final 8 outputs)
    sweep2_out<<<1, 256>>>(ctx, h, mu, sg, epw, bmu, bsg, epb, out);
}

// round 11
// speedup vs baseline: 2.0650x; 2.0648x over previous
#include <cuda_runtime.h>
#include <cuda_fp16.h>
#include <math.h>
#include <stdint.h>

#define DD 7686
#define HH 512
#define OO 8
#define NN 8206
#define MM 2048
#define KP 7712        // padded K pitch in elements (241 * 32)
#define NKH 241        // K-tiles of 32 halfs
#define NPAD 7808      // padded N rows for B operand (61 * 128)

// ---------------------------------------------------------------------------
// Scratch (device globals; uint16_t to avoid __half ctor issues)
// ---------------------------------------------------------------------------
__device__ __align__(1024) uint16_t g_Xh [MM * KP];      // X   fp16 [2048, KP]
__device__ __align__(1024) uint16_t g_Wth[NPAD * KP];    // W^T fp16 [7808, KP] (Wq then Wk)
__device__ __align__(1024) uint16_t g_Qh [MM * KP];      // Q   fp16
__device__ __align__(1024) uint16_t g_Kh [MM * KP];      // K   fp16
__device__ __align__(1024) float    g_S  [MM * MM];
__device__ __align__(256) float g_rmax[MM], g_rscale[MM];
__device__ __align__(256) float g_partW[8 * MM], g_w[MM];
__device__ __align__(256) float g_partU[8 * DD], g_u[DD];
__device__ __align__(256) float g_partC[16 * DD], g_ctx[DD];
__device__ __align__(256) float g_partH[64 * 520], g_h[520];

// ---------------------------------------------------------------------------
// cp.async
// ---------------------------------------------------------------------------
__device__ __forceinline__ void cp16(unsigned d, const void* s) {
    asm volatile("cp.async.cg.shared.global [%0], [%1], 16;" :: "r"(d), "l"(s));
}
#define CP_COMMIT() asm volatile("cp.async.commit_group;" ::)
#define CP_WAIT1()  asm volatile("cp.async.wait_group 1;" ::)
#define CP_WAIT0()  asm volatile("cp.async.wait_group 0;" ::)

// m16n8k16 fp16 MMA, fp32 accumulate
__device__ __forceinline__ void mma16(float c[4], const unsigned a[4], const unsigned b[2]) {
    asm volatile(
        "mma.sync.aligned.m16n8k16.row.col.f32.f16.f16.f32 "
        "{%0,%1,%2,%3}, {%4,%5,%6,%7}, {%8,%9}, {%0,%1,%2,%3};\n"
        : "+f"(c[0]), "+f"(c[1]), "+f"(c[2]), "+f"(c[3])
        : "r"(a[0]), "r"(a[1]), "r"(a[2]), "r"(a[3]), "r"(b[0]), "r"(b[1]));
}

// ---------------------------------------------------------------------------
// fp16 GEMM: C[2048, Nn] = A[2048, KP] * B[rows, KP]^T   (both K-contiguous,
// zero-padded to KP so the K loop needs no guards).
// Block 128x128, K-tile 32, 8 warps (warp tile 64x32), double-buffered.
// WH=1: write fp16 C with bias (pads zeroed). WH=0: write fp32 C * scale.
// ---------------------------------------------------------------------------
template <int WH>
__global__ void __launch_bounds__(256, 2)
gemm_h(const uint16_t* __restrict__ A, const uint16_t* __restrict__ B,
       float* __restrict__ Cf, uint16_t* __restrict__ Ch,
       const float* __restrict__ bias, float scale, int Nn, int Cpitch)
{
    constexpr int ST   = 40;           // smem row stride in halfs (80B: conflict-free)
    constexpr int ELE  = 128 * ST;     // halfs per tile buffer

    __shared__ uint16_t As[2][ELE];
    __shared__ uint16_t Bs[2][ELE];

    const int t    = threadIdx.x;
    const int warp = t >> 5, lane = t & 31;
    const int grp  = lane >> 2, tig = lane & 3;
    const int wm   = warp & 1, wn = warp >> 1;
    const int bM   = blockIdx.x, bN = blockIdx.y;

    const unsigned sA = (unsigned)__cvta_generic_to_shared(&As[0][0]);
    const unsigned sB = (unsigned)__cvta_generic_to_shared(&Bs[0][0]);

    float acc[4][4][4];
#pragma unroll
    for (int i = 0; i < 4; i++)
#pragma unroll
        for (int j = 0; j < 4; j++)
#pragma unroll
            for (int k = 0; k < 4; k++) acc[i][j][k] = 0.f;

    auto loadTile = [&](int buf, int k0) {
#pragma unroll
        for (int i = 0; i < 2; i++) {                 // A: 512 chunks of 8 halfs
            int c = t + 256 * i;
            int row = c >> 2, kc = (c & 3) << 3;
            cp16(sA + (unsigned)(buf * ELE + row * ST + kc) * 2u,
                 A + (size_t)(bM * 128 + row) * KP + k0 + kc);
        }
#pragma unroll
        for (int i = 0; i < 2; i++) {                 // B: 512 chunks
            int c = t + 256 * i;
            int row = c >> 2, kc = (c & 3) << 3;
            cp16(sB + (unsigned)(buf * ELE + row * ST + kc) * 2u,
                 B + (size_t)(bN * 128 + row) * KP + k0 + kc);
        }
    };

    loadTile(0, 0);
    CP_COMMIT();

    for (int kt = 0; kt < NKH; kt++) {
        if (kt + 1 < NKH) {
            loadTile((kt + 1) & 1, (kt + 1) << 5);
            CP_COMMIT();
            CP_WAIT1();
        } else {
            CP_WAIT0();
        }
        __syncthreads();

        const uint16_t* Ab = As[kt & 1];
        const uint16_t* Bb = Bs[kt & 1];

#pragma unroll
        for (int s = 0; s < 2; s++) {                 // two k16 steps per k32 tile
            const int kb = s << 4;
            unsigned a[4][4], b[4][2];
#pragma unroll
            for (int im = 0; im < 4; im++) {
                int r = wm * 64 + im * 16 + grp;
                a[im][0] = *(const unsigned*)&Ab[r * ST + kb + 2 * tig];
                a[im][1] = *(const unsigned*)&Ab[(r + 8) * ST + kb + 2 * tig];
                a[im][2] = *(const unsigned*)&Ab[r * ST + kb + 2 * tig + 8];
                a[im][3] = *(const unsigned*)&Ab[(r + 8) * ST + kb + 2 * tig + 8];
            }
#pragma unroll
            for (int jn = 0; jn < 4; jn++) {
                int cc = wn * 32 + jn * 8 + grp;
                b[jn][0] = *(const unsigned*)&Bb[cc * ST + kb + 2 * tig];
                b[jn][1] = *(const unsigned*)&Bb[cc * ST + kb + 2 * tig + 8];
            }
#pragma unroll
            for (int im = 0; im < 4; im++)
#pragma unroll
                for (int jn = 0; jn < 4; jn++)
                    mma16(acc[im][jn], a[im], b[jn]);
        }
        __syncthreads();
    }

    // ---- epilogue ----
#pragma unroll
    for (int im = 0; im < 4; im++) {
#pragma unroll
        for (int jn = 0; jn < 4; jn++) {
            int r  = bM * 128 + wm * 64 + im * 16 + grp;
            int cc = bN * 128 + wn * 32 + jn * 8 + (tig << 1);
#pragma unroll
            for (int e = 0; e < 2; e++) {
                int n = cc + e;
                float v0 = acc[im][jn][0 + e];   // row r
                float v1 = acc[im][jn][2 + e];   // row r+8
                if (WH) {
                    if (n < Nn) {
                        float bb = bias[n];
                        Ch[(size_t)r * Cpitch + n] =
                            __half_as_ushort(__float2half_rn(v0 + bb));
                        Ch[(size_t)(r + 8) * Cpitch + n] =
                            __half_as_ushort(__float2half_rn(v1 + bb));
                    } else if (n < Cpitch) {     // zero the K-pad columns
                        Ch[(size_t)r * Cpitch + n] = 0;
                        Ch[(size_t)(r + 8) * Cpitch + n] = 0;
                    }
                } else {
                    if (n < Nn) {
                        Cf[(size_t)r * Cpitch + n] = v0 * scale;
                        Cf[(size_t)(r + 8) * Cpitch + n] = v1 * scale;
                    }
                }
            }
        }
    }
}

// ---- X fp32 -> fp16 padded ----
__global__ void conv_x(const float* __restrict__ X, uint16_t* __restrict__ Xh)
{
    const int j = blockIdx.x * 256 + threadIdx.x;
    const int m = blockIdx.y;
    if (j >= KP) return;
    float v = (j < DD) ? X[(size_t)m * DD + j] : 0.f;
    Xh[(size_t)m * KP + j] = __half_as_ushort(__float2half_rn(v));
}

// ---- W fp32 [k][n] -> W^T fp16 [n][KP] padded (rows to NPAD) ----
__global__ void convT_w(const float* __restrict__ W, uint16_t* __restrict__ Wt)
{
    __shared__ float tile[32][33];
    const int kx = blockIdx.x * 32, ny = blockIdx.y * 32;
    const int tx = threadIdx.x, ty = threadIdx.y;
#pragma unroll
    for (int i = 0; i < 4; i++) {
        int k = kx + ty + i * 8, n = ny + tx;
        tile[ty + i * 8][tx] = (k < DD && n < DD) ? W[(size_t)k * DD + n] : 0.f;
    }
    __syncthreads();
#pragma unroll
    for (int i = 0; i < 4; i++) {
        int n = ny + ty + i * 8, k = kx + tx;
        if (n < NPAD)
            Wt[(size_t)n * KP + k] = __half_as_ushort(__float2half_rn(tile[tx][ty + i * 8]));
    }
}

// ---- softmax / reductions / graph sweeps (unchanged from passing R5) ----
__global__ void row_softmax_stats(const float* __restrict__ S, float* __restrict__ rmax,
                                  float* __restrict__ rscale)
{
    __shared__ float red[256];
    const int m = blockIdx.x, t = threadIdx.x;
    const float* row = S + (size_t)m * MM;
    float mx = -3.402823e38f;
    for (int j = t; j < MM; j += 256) mx = fmaxf(mx, row[j]);
    red[t] = mx; __syncthreads();
    for (int s = 128; s > 0; s >>= 1) { if (t < s) red[t] = fmaxf(red[t], red[t + s]); __syncthreads(); }
    mx = red[0]; __syncthreads();
    float sm = 0.f;
    for (int j = t; j < MM; j += 256) sm += __expf(row[j] - mx);
    red[t] = sm; __syncthreads();
    for (int s = 128; s > 0; s >>= 1) { if (t < s) red[t] += red[t + s]; __syncthreads(); }
    if (t == 0) { rmax[m] = mx; rscale[m] = 1.f / (red[0] * (float)MM); }
}
__global__ void colmean_partial(const float* __restrict__ S, const float* __restrict__ rmax,
                                const float* __restrict__ rscale, float* __restrict__ part)
{
    const int j = blockIdx.x * 256 + threadIdx.x, mb = blockIdx.y, m0 = mb * 256;
    float acc = 0.f;
#pragma unroll 4
    for (int m = m0; m < m0 + 256; m++)
        acc += __expf(S[(size_t)m * MM + j] - rmax[m]) * rscale[m];
    part[mb * MM + j] = acc;
}
__global__ void reduce_w(const float* __restrict__ part, float* __restrict__ w)
{
    const int j = blockIdx.x * 256 + threadIdx.x;
    float s = 0.f;
#pragma unroll
    for (int c = 0; c < 8; c++) s += part[c * MM + j];
    w[j] = s;
}
__global__ void wx_partial(const float* __restrict__ X, const float* __restrict__ w,
                           float* __restrict__ part)
{
    const int d = blockIdx.x * 256 + threadIdx.x, mb = blockIdx.y;
    if (d >= DD) return;
    const int m0 = mb * 256;
    float acc = 0.f;
#pragma unroll 4
    for (int m = m0; m < m0 + 256; m++) acc += w[m] * X[(size_t)m * DD + d];
    part[mb * DD + d] = acc;
}
__global__ void reduce_u(const float* __restrict__ part, float* __restrict__ u)
{
    const int d = blockIdx.x * 256 + threadIdx.x;
    if (d >= DD) return;
    float s = 0.f;
#pragma unroll
    for (int c = 0; c < 8; c++) s += part[c * DD + d];
    u[d] = s;
}
__global__ void uwv_partial(const float* __restrict__ u, const float* __restrict__ Wv,
                            float* __restrict__ part)
{
    const int n = blockIdx.x * 256 + threadIdx.x, kb = blockIdx.y;
    if (n >= DD) return;
    const int k0 = kb * 481, k1 = (k0 + 481 < DD) ? (k0 + 481) : DD;
    float acc = 0.f;
    for (int k = k0; k < k1; k++) acc += u[k] * Wv[(size_t)k * DD + n];
    part[kb * DD + n] = acc;
}
__global__ void reduce_ctx(const float* __restrict__ part, const float* __restrict__ bv,
                           float* __restrict__ ctx)
{
    const int n = blockIdx.x * 256 + threadIdx.x;
    if (n >= DD) return;
    float s = 0.f;
#pragma unroll
    for (int c = 0; c < 16; c++) s += part[c * DD + n];
    ctx[n] = s + bv[n];
}
__global__ void sweep1_partial(const float* __restrict__ ctx, const float* __restrict__ mu,
                               const float* __restrict__ sg, const float* __restrict__ ep,
                               float* __restrict__ part)
{
    const int j = blockIdx.x * 256 + threadIdx.x, ib = blockIdx.y;
    if (j >= HH + OO) return;
    const int i0 = ib * 121, i1 = (i0 + 121 < DD) ? (i0 + 121) : DD;
    float acc = 0.f;
    for (int i = i0; i < i1; i++) {
        size_t off = (size_t)i * NN + DD + j;
        acc += ctx[i] * (mu[off] + sg[off] * ep[off]);
    }
    part[ib * (HH + OO) + j] = acc;
}
__global__ void reduce_h(const float* __restrict__ part, const float* __restrict__ bmu,
                         const float* __restrict__ bsg, const float* __restrict__ epb,
                         float* __restrict__ h)
{
    const int j = blockIdx.x * 256 + threadIdx.x;
    if (j >= HH + OO) return;
    float s = 0.f;
#pragma unroll
    for (int c = 0; c < 64; c++) s += part[c * (HH + OO) + j];
    s += bmu[DD + j] + bsg[DD + j] * epb[DD + j];
    h[j] = tanhf(s);
}
__global__ void sweep2_out(const float* __restrict__ ctx, const float* __restrict__ h,
                           const float* __restrict__ mu, const float* __restrict__ sg,
                           const float* __restrict__ ep, const float* __restrict__ bmu,
                           const float* __restrict__ bsg, const float* __restrict__ epb,
                           float* __restrict__ out)
{
    __shared__ float red[8][256];
    const int t = threadIdx.x;
    float acc[8];
#pragma unroll
    for (int o = 0; o < 8; o++) acc[o] = 0.f;
    for (int i = t; i < NN; i += 256) {
        float zi = (i < DD) ? ctx[i] : h[i - DD];
        size_t base = (size_t)i * NN + (DD + HH);
#pragma unroll
        for (int o = 0; o < 8; o++) acc[o] += zi * (mu[base + o] + sg[base + o] * ep[base + o]);
    }
#pragma unroll
    for (int o = 0; o < 8; o++) red[o][t] = acc[o];
    __syncthreads();
    for (int s = 128; s > 0; s >>= 1) {
        if (t < s)
#pragma unroll
            for (int o = 0; o < 8; o++) red[o][t] += red[o][t + s];
        __syncthreads();
    }
    if (t < 8) {
        float b2 = bmu[DD + HH + t] + bsg[DD + HH + t] * epb[DD + HH + t];
        out[t] = 1.f / (1.f + expf(-tanhf(red[t][0] + b2)));
    }
}

// ---------------------------------------------------------------------------
extern "C" void kernel_launch(void* const* d_in, const int* in_sizes, int n_in,
                              void* d_out, int out_size)
{
    const float* X   = (const float*)d_in[0];
    const float* Wq  = (const float*)d_in[1];
    const float* bq  = (const float*)d_in[2];
    const float* Wk  = (const float*)d_in[3];
    const float* bk  = (const float*)d_in[4];
    const float* Wv  = (const float*)d_in[5];
    const float* bv  = (const float*)d_in[6];
    const float* mu  = (const float*)d_in[7];
    const float* sg  = (const float*)d_in[8];
    const float* bmu = (const float*)d_in[9];
    const float* bsg = (const float*)d_in[10];
    const float* epw = (const float*)d_in[11];
    const float* epb = (const float*)d_in[12];
    float* out = (float*)d_out;

    uint16_t *Xh, *Wth, *Qh, *Kh;
    float *S, *rmax, *rscale, *partW, *w, *partU, *u, *partC, *ctx, *partH, *h;
    cudaGetSymbolAddress((void**)&Xh,  g_Xh);
    cudaGetSymbolAddress((void**)&Wth, g_Wth);
    cudaGetSymbolAddress((void**)&Qh,  g_Qh);
    cudaGetSymbolAddress((void**)&Kh,  g_Kh);
    cudaGetSymbolAddress((void**)&S,   g_S);
    cudaGetSymbolAddress((void**)&rmax, g_rmax);
    cudaGetSymbolAddress((void**)&rscale, g_rscale);
    cudaGetSymbolAddress((void**)&partW, g_partW);
    cudaGetSymbolAddress((void**)&w, g_w);
    cudaGetSymbolAddress((void**)&partU, g_partU);
    cudaGetSymbolAddress((void**)&u, g_u);
    cudaGetSymbolAddress((void**)&partC, g_partC);
    cudaGetSymbolAddress((void**)&ctx, g_ctx);
    cudaGetSymbolAddress((void**)&partH, g_partH);
    cudaGetSymbolAddress((void**)&h, g_h);

    const float inv_sqrt_d = 1.0f / sqrtf((float)DD);
    const dim3 tb32(32, 8);
    const dim3 tgw(KP / 32, NPAD / 32);

    // fp16 conversions
    conv_x<<<dim3((KP + 255) / 256, MM), 256>>>(X, Xh);

    // Q = X Wq + bq   (fp16 out, pads zeroed)
    convT_w<<<tgw, tb32>>>(Wq, Wth);
    gemm_h<1><<<dim3(16, 61), 256>>>(Xh, Wth, nullptr, Qh, bq, 1.0f, DD, KP);
    // K = X Wk + bk
    convT_w<<<tgw, tb32>>>(Wk, Wth);
    gemm_h<1><<<dim3(16, 61), 256>>>(Xh, Wth, nullptr, Kh, bk, 1.0f, DD, KP);
    // S = Q K^T / sqrt(D)   (fp32 out)
    gemm_h<0><<<dim3(16, 16), 256>>>(Qh, Kh, S, nullptr, nullptr, inv_sqrt_d, MM, MM);

    row_softmax_stats<<<MM, 256>>>(S, rmax, rscale);
    colmean_partial<<<dim3(8, 8), 256>>>(S, rmax, rscale, partW);
    reduce_w<<<8, 256>>>(partW, w);
    wx_partial<<<dim3(31, 8), 256>>>(X, w, partU);
    reduce_u<<<31, 256>>>(partU, u);
    uwv_partial<<<dim3(31, 16), 256>>>(u, Wv, partC);
    reduce_ctx<<<31, 256>>>(partC, bv, ctx);
    sweep1_partial<<<dim3(3, 64), 256>>>(ctx, mu, sg, epw, partH);
    reduce_h<<<3, 256>>>(partH, bmu, bsg, epb, h);
    sweep2_out<<<1, 256>>>(ctx, h, mu, sg, epw, bmu, bsg, epb, out);
}

// round 12
// speedup vs baseline: 2.1018x; 1.0178x over previous
#include <cuda_runtime.h>
#include <cuda_fp16.h>
#include <math.h>
#include <stdint.h>

#define DD 7686
#define HH 512
#define OO 8
#define NN 8206
#define MM 2048
#define KP 7712        // padded K pitch in elements (241 * 32)
#define NKH 241        // K-tiles of 32 halfs
#define NPAD 7808      // padded N rows for B operand (61 * 128)

// ---------------------------------------------------------------------------
// Scratch (device globals)
// ---------------------------------------------------------------------------
__device__ __align__(1024) uint16_t g_Xh [MM * KP];      // X   fp16 [2048, KP]
__device__ __align__(1024) uint16_t g_Wth[NPAD * KP];    // W^T fp16 (Wq then Wk)
__device__ __align__(1024) uint16_t g_Qh [MM * KP];      // Q   fp16
__device__ __align__(1024) uint16_t g_Kh [MM * KP];      // K   fp16
__device__ __align__(1024) float    g_S  [MM * MM];
__device__ __align__(256) float g_rmax[MM], g_rscale[MM];
__device__ __align__(256) float g_partW[8 * MM], g_w[MM];
__device__ __align__(256) float g_partU[8 * DD], g_u[DD];
__device__ __align__(256) float g_partC[16 * DD], g_ctx[DD];
__device__ __align__(256) float g_partH[64 * 520], g_h[520];

// ---------------------------------------------------------------------------
// cp.async
// ---------------------------------------------------------------------------
__device__ __forceinline__ void cp16(unsigned d, const void* s) {
    asm volatile("cp.async.cg.shared.global [%0], [%1], 16;" :: "r"(d), "l"(s));
}
#define CP_COMMIT() asm volatile("cp.async.commit_group;" ::)

// m16n8k16 fp16 MMA, fp32 accumulate
__device__ __forceinline__ void mma16(float c[4], const unsigned a[4], const unsigned b[2]) {
    asm volatile(
        "mma.sync.aligned.m16n8k16.row.col.f32.f16.f16.f32 "
        "{%0,%1,%2,%3}, {%4,%5,%6,%7}, {%8,%9}, {%0,%1,%2,%3};\n"
        : "+f"(c[0]), "+f"(c[1]), "+f"(c[2]), "+f"(c[3])
        : "r"(a[0]), "r"(a[1]), "r"(a[2]), "r"(a[3]), "r"(b[0]), "r"(b[1]));
}

// ---------------------------------------------------------------------------
// fp16 GEMM: C[2048, Nn] = A[2048, KP] * B[rows, KP]^T   (both K-contiguous,
// zero-padded to KP: no K guards). Block 128x128, K-tile 32, 8 warps
// (warp tile 64x32). 4-stage cp.async pipeline, ONE __syncthreads per iter.
// WH=1: fp16 C with bias (pads zeroed). WH=0: fp32 C * scale.
// ---------------------------------------------------------------------------
#define ST   40                       // smem row stride in halfs (80B, conflict-free)
#define ELE  (128 * ST)               // halfs per operand per stage (10240B)
#define SMEM_H (4 * 2 * ELE * 2)      // 81920 bytes dynamic smem

template <int WH>
__global__ void __launch_bounds__(256, 2)
gemm_h(const uint16_t* __restrict__ A, const uint16_t* __restrict__ B,
       float* __restrict__ Cf, uint16_t* __restrict__ Ch,
       const float* __restrict__ bias, float scale, int Nn, int Cpitch)
{
    extern __shared__ __align__(128) uint16_t sm[];
    uint16_t* As = sm;                 // 4 stages x ELE
    uint16_t* Bs = sm + 4 * ELE;       // 4 stages x ELE

    const int t    = threadIdx.x;
    const int warp = t >> 5, lane = t & 31;
    const int grp  = lane >> 2, tig = lane & 3;
    const int wm   = warp & 1, wn = warp >> 1;
    const int bM   = blockIdx.x, bN = blockIdx.y;

    const unsigned sA = (unsigned)__cvta_generic_to_shared(As);
    const unsigned sB = (unsigned)__cvta_generic_to_shared(Bs);

    float acc[4][4][4];
#pragma unroll
    for (int i = 0; i < 4; i++)
#pragma unroll
        for (int j = 0; j < 4; j++)
#pragma unroll
            for (int k = 0; k < 4; k++) acc[i][j][k] = 0.f;

    auto loadTile = [&](int kt) {
        const int buf = kt & 3, k0 = kt << 5;
#pragma unroll
        for (int i = 0; i < 2; i++) {                 // A: 512 chunks of 8 halfs
            int c = t + 256 * i;
            int row = c >> 2, kc = (c & 3) << 3;
            cp16(sA + (unsigned)(buf * ELE + row * ST + kc) * 2u,
                 A + (size_t)(bM * 128 + row) * KP + k0 + kc);
        }
#pragma unroll
        for (int i = 0; i < 2; i++) {                 // B: 512 chunks
            int c = t + 256 * i;
            int row = c >> 2, kc = (c & 3) << 3;
            cp16(sB + (unsigned)(buf * ELE + row * ST + kc) * 2u,
                 B + (size_t)(bN * 128 + row) * KP + k0 + kc);
        }
    };

    loadTile(0); CP_COMMIT();
    loadTile(1); CP_COMMIT();
    loadTile(2); CP_COMMIT();

    for (int kt = 0; kt < NKH; kt++) {
        // wait until this thread's tile-kt group completed
        if (kt < NKH - 2)      asm volatile("cp.async.wait_group 2;" ::);
        else if (kt < NKH - 1) asm volatile("cp.async.wait_group 1;" ::);
        else                   asm volatile("cp.async.wait_group 0;" ::);
        __syncthreads();   // tile kt visible to all; compute(kt-1) done by all

        if (kt + 3 < NKH) { loadTile(kt + 3); CP_COMMIT(); }

        const uint16_t* Ab = As + (kt & 3) * ELE;
        const uint16_t* Bb = Bs + (kt & 3) * ELE;

#pragma unroll
        for (int s = 0; s < 2; s++) {                 // two k16 steps per k32 tile
            const int kb = s << 4;
            unsigned a[4][4], b[4][2];
#pragma unroll
            for (int im = 0; im < 4; im++) {
                int r = wm * 64 + im * 16 + grp;
                a[im][0] = *(const unsigned*)&Ab[r * ST + kb + 2 * tig];
                a[im][1] = *(const unsigned*)&Ab[(r + 8) * ST + kb + 2 * tig];
                a[im][2] = *(const unsigned*)&Ab[r * ST + kb + 2 * tig + 8];
                a[im][3] = *(const unsigned*)&Ab[(r + 8) * ST + kb + 2 * tig + 8];
            }
#pragma unroll
            for (int jn = 0; jn < 4; jn++) {
                int cc = wn * 32 + jn * 8 + grp;
                b[jn][0] = *(const unsigned*)&Bb[cc * ST + kb + 2 * tig];
                b[jn][1] = *(const unsigned*)&Bb[cc * ST + kb + 2 * tig + 8];
            }
#pragma unroll
            for (int im = 0; im < 4; im++)
#pragma unroll
                for (int jn = 0; jn < 4; jn++)
                    mma16(acc[im][jn], a[im], b[jn]);
        }
    }

    // ---- epilogue ----
#pragma unroll
    for (int im = 0; im < 4; im++) {
#pragma unroll
        for (int jn = 0; jn < 4; jn++) {
            int r  = bM * 128 + wm * 64 + im * 16 + grp;
            int cc = bN * 128 + wn * 32 + jn * 8 + (tig << 1);
#pragma unroll
            for (int e = 0; e < 2; e++) {
                int n = cc + e;
                float v0 = acc[im][jn][0 + e];   // row r
                float v1 = acc[im][jn][2 + e];   // row r+8
                if (WH) {
                    if (n < Nn) {
                        float bb = bias[n];
                        Ch[(size_t)r * Cpitch + n] =
                            __half_as_ushort(__float2half_rn(v0 + bb));
                        Ch[(size_t)(r + 8) * Cpitch + n] =
                            __half_as_ushort(__float2half_rn(v1 + bb));
                    } else if (n < Cpitch) {     // zero the K-pad columns
                        Ch[(size_t)r * Cpitch + n] = 0;
                        Ch[(size_t)(r + 8) * Cpitch + n] = 0;
                    }
                } else {
                    if (n < Nn) {
                        Cf[(size_t)r * Cpitch + n] = v0 * scale;
                        Cf[(size_t)(r + 8) * Cpitch + n] = v1 * scale;
                    }
                }
            }
        }
    }
}

// ---- X fp32 -> fp16 padded ----
__global__ void conv_x(const float* __restrict__ X, uint16_t* __restrict__ Xh)
{
    const int j = blockIdx.x * 256 + threadIdx.x;
    const int m = blockIdx.y;
    if (j >= KP) return;
    float v = (j < DD) ? X[(size_t)m * DD + j] : 0.f;
    Xh[(size_t)m * KP + j] = __half_as_ushort(__float2half_rn(v));
}

// ---- W fp32 [k][n] -> W^T fp16 [n][KP] padded (rows to NPAD) ----
__global__ void convT_w(const float* __restrict__ W, uint16_t* __restrict__ Wt)
{
    __shared__ float tile[32][33];
    const int kx = blockIdx.x * 32, ny = blockIdx.y * 32;
    const int tx = threadIdx.x, ty = threadIdx.y;
#pragma unroll
    for (int i = 0; i < 4; i++) {
        int k = kx + ty + i * 8, n = ny + tx;
        tile[ty + i * 8][tx] = (k < DD && n < DD) ? W[(size_t)k * DD + n] : 0.f;
    }
    __syncthreads();
#pragma unroll
    for (int i = 0; i < 4; i++) {
        int n = ny + ty + i * 8, k = kx + tx;
        if (n < NPAD)
            Wt[(size_t)n * KP + k] = __half_as_ushort(__float2half_rn(tile[tx][ty + i * 8]));
    }
}

// ---- softmax / reductions / graph sweeps (unchanged, passing) ----
__global__ void row_softmax_stats(const float* __restrict__ S, float* __restrict__ rmax,
                                  float* __restrict__ rscale)
{
    __shared__ float red[256];
    const int m = blockIdx.x, t = threadIdx.x;
    const float* row = S + (size_t)m * MM;
    float mx = -3.402823e38f;
    for (int j = t; j < MM; j += 256) mx = fmaxf(mx, row[j]);
    red[t] = mx; __syncthreads();
    for (int s = 128; s > 0; s >>= 1) { if (t < s) red[t] = fmaxf(red[t], red[t + s]); __syncthreads(); }
    mx = red[0]; __syncthreads();
    float sm = 0.f;
    for (int j = t; j < MM; j += 256) sm += __expf(row[j] - mx);
    red[t] = sm; __syncthreads();
    for (int s = 128; s > 0; s >>= 1) { if (t < s) red[t] += red[t + s]; __syncthreads(); }
    if (t == 0) { rmax[m] = mx; rscale[m] = 1.f / (red[0] * (float)MM); }
}
__global__ void colmean_partial(const float* __restrict__ S, const float* __restrict__ rmax,
                                const float* __restrict__ rscale, float* __restrict__ part)
{
    const int j = blockIdx.x * 256 + threadIdx.x, mb = blockIdx.y, m0 = mb * 256;
    float acc = 0.f;
#pragma unroll 4
    for (int m = m0; m < m0 + 256; m++)
        acc += __expf(S[(size_t)m * MM + j] - rmax[m]) * rscale[m];
    part[mb * MM + j] = acc;
}
__global__ void reduce_w(const float* __restrict__ part, float* __restrict__ w)
{
    const int j = blockIdx.x * 256 + threadIdx.x;
    float s = 0.f;
#pragma unroll
    for (int c = 0; c < 8; c++) s += part[c * MM + j];
    w[j] = s;
}
__global__ void wx_partial(const float* __restrict__ X, const float* __restrict__ w,
                           float* __restrict__ part)
{
    const int d = blockIdx.x * 256 + threadIdx.x, mb = blockIdx.y;
    if (d >= DD) return;
    const int m0 = mb * 256;
    float acc = 0.f;
#pragma unroll 4
    for (int m = m0; m < m0 + 256; m++) acc += w[m] * X[(size_t)m * DD + d];
    part[mb * DD + d] = acc;
}
__global__ void reduce_u(const float* __restrict__ part, float* __restrict__ u)
{
    const int d = blockIdx.x * 256 + threadIdx.x;
    if (d >= DD) return;
    float s = 0.f;
#pragma unroll
    for (int c = 0; c < 8; c++) s += part[c * DD + d];
    u[d] = s;
}
__global__ void uwv_partial(const float* __restrict__ u, const float* __restrict__ Wv,
                            float* __restrict__ part)
{
    const int n = blockIdx.x * 256 + threadIdx.x, kb = blockIdx.y;
    if (n >= DD) return;
    const int k0 = kb * 481, k1 = (k0 + 481 < DD) ? (k0 + 481) : DD;
    float acc = 0.f;
    for (int k = k0; k < k1; k++) acc += u[k] * Wv[(size_t)k * DD + n];
    part[kb * DD + n] = acc;
}
__global__ void reduce_ctx(const float* __restrict__ part, const float* __restrict__ bv,
                           float* __restrict__ ctx)
{
    const int n = blockIdx.x * 256 + threadIdx.x;
    if (n >= DD) return;
    float s = 0.f;
#pragma unroll
    for (int c = 0; c < 16; c++) s += part[c * DD + n];
    ctx[n] = s + bv[n];
}
__global__ void sweep1_partial(const float* __restrict__ ctx, const float* __restrict__ mu,
                               const float* __restrict__ sg, const float* __restrict__ ep,
                               float* __restrict__ part)
{
    const int j = blockIdx.x * 256 + threadIdx.x, ib = blockIdx.y;
    if (j >= HH + OO) return;
    const int i0 = ib * 121, i1 = (i0 + 121 < DD) ? (i0 + 121) : DD;
    float acc = 0.f;
    for (int i = i0; i < i1; i++) {
        size_t off = (size_t)i * NN + DD + j;
        acc += ctx[i] * (mu[off] + sg[off] * ep[off]);
    }
    part[ib * (HH + OO) + j] = acc;
}
__global__ void reduce_h(const float* __restrict__ part, const float* __restrict__ bmu,
                         const float* __restrict__ bsg, const float* __restrict__ epb,
                         float* __restrict__ h)
{
    const int j = blockIdx.x * 256 + threadIdx.x;
    if (j >= HH + OO) return;
    float s = 0.f;
#pragma unroll
    for (int c = 0; c < 64; c++) s += part[c * (HH + OO) + j];
    s += bmu[DD + j] + bsg[DD + j] * epb[DD + j];
    h[j] = tanhf(s);
}
__global__ void sweep2_out(const float* __restrict__ ctx, const float* __restrict__ h,
                           const float* __restrict__ mu, const float* __restrict__ sg,
                           const float* __restrict__ ep, const float* __restrict__ bmu,
                           const float* __restrict__ bsg, const float* __restrict__ epb,
                           float* __restrict__ out)
{
    __shared__ float red[8][256];
    const int t = threadIdx.x;
    float acc[8];
#pragma unroll
    for (int o = 0; o < 8; o++) acc[o] = 0.f;
    for (int i = t; i < NN; i += 256) {
        float zi = (i < DD) ? ctx[i] : h[i - DD];
        size_t base = (size_t)i * NN + (DD + HH);
#pragma unroll
        for (int o = 0; o < 8; o++) acc[o] += zi * (mu[base + o] + sg[base + o] * ep[base + o]);
    }
#pragma unroll
    for (int o = 0; o < 8; o++) red[o][t] = acc[o];
    __syncthreads();
    for (int s = 128; s > 0; s >>= 1) {
        if (t < s)
#pragma unroll
            for (int o = 0; o < 8; o++) red[o][t] += red[o][t + s];
        __syncthreads();
    }
    if (t < 8) {
        float b2 = bmu[DD + HH + t] + bsg[DD + HH + t] * epb[DD + HH + t];
        out[t] = 1.f / (1.f + expf(-tanhf(red[t][0] + b2)));
    }
}

// ---------------------------------------------------------------------------
extern "C" void kernel_launch(void* const* d_in, const int* in_sizes, int n_in,
                              void* d_out, int out_size)
{
    const float* X   = (const float*)d_in[0];
    const float* Wq  = (const float*)d_in[1];
    const float* bq  = (const float*)d_in[2];
    const float* Wk  = (const float*)d_in[3];
    const float* bk  = (const float*)d_in[4];
    const float* Wv  = (const float*)d_in[5];
    const float* bv  = (const float*)d_in[6];
    const float* mu  = (const float*)d_in[7];
    const float* sg  = (const float*)d_in[8];
    const float* bmu = (const float*)d_in[9];
    const float* bsg = (const float*)d_in[10];
    const float* epw = (const float*)d_in[11];
    const float* epb = (const float*)d_in[12];
    float* out = (float*)d_out;

    uint16_t *Xh, *Wth, *Qh, *Kh;
    float *S, *rmax, *rscale, *partW, *w, *partU, *u, *partC, *ctx, *partH, *h;
    cudaGetSymbolAddress((void**)&Xh,  g_Xh);
    cudaGetSymbolAddress((void**)&Wth, g_Wth);
    cudaGetSymbolAddress((void**)&Qh,  g_Qh);
    cudaGetSymbolAddress((void**)&Kh,  g_Kh);
    cudaGetSymbolAddress((void**)&S,   g_S);
    cudaGetSymbolAddress((void**)&rmax, g_rmax);
    cudaGetSymbolAddress((void**)&rscale, g_rscale);
    cudaGetSymbolAddress((void**)&partW, g_partW);
    cudaGetSymbolAddress((void**)&w, g_w);
    cudaGetSymbolAddress((void**)&partU, g_partU);
    cudaGetSymbolAddress((void**)&u, g_u);
    cudaGetSymbolAddress((void**)&partC, g_partC);
    cudaGetSymbolAddress((void**)&ctx, g_ctx);
    cudaGetSymbolAddress((void**)&partH, g_partH);
    cudaGetSymbolAddress((void**)&h, g_h);

    cudaFuncSetAttribute(gemm_h<1>, cudaFuncAttributeMaxDynamicSharedMemorySize, SMEM_H);
    cudaFuncSetAttribute(gemm_h<0>, cudaFuncAttributeMaxDynamicSharedMemorySize, SMEM_H);

    const float inv_sqrt_d = 1.0f / sqrtf((float)DD);
    const dim3 tb32(32, 8);
    const dim3 tgw(KP / 32, NPAD / 32);

    // fp16 conversions
    conv_x<<<dim3((KP + 255) / 256, MM), 256>>>(X, Xh);

    // Q = X Wq + bq   (fp16 out, pads zeroed)
    convT_w<<<tgw, tb32>>>(Wq, Wth);
    gemm_h<1><<<dim3(16, 61), 256, SMEM_H>>>(Xh, Wth, nullptr, Qh, bq, 1.0f, DD, KP);
    // K = X Wk + bk
    convT_w<<<tgw, tb32>>>(Wk, Wth);
    gemm_h<1><<<dim3(16, 61), 256, SMEM_H>>>(Xh, Wth, nullptr, Kh, bk, 1.0f, DD, KP);
    // S = Q K^T / sqrt(D)   (fp32 out)
    gemm_h<0><<<dim3(16, 16), 256, SMEM_H>>>(Qh, Kh, S, nullptr, nullptr, inv_sqrt_d, MM, MM);

    row_softmax_stats<<<MM, 256>>>(S, rmax, rscale);
    colmean_partial<<<dim3(8, 8), 256>>>(S, rmax, rscale, partW);
    reduce_w<<<8, 256>>>(partW, w);
    wx_partial<<<dim3(31, 8), 256>>>(X, w, partU);
    reduce_u<<<31, 256>>>(partU, u);
    uwv_partial<<<dim3(31, 16), 256>>>(u, Wv, partC);
    reduce_ctx<<<31, 256>>>(partC, bv, ctx);
    sweep1_partial<<<dim3(3, 64), 256>>>(ctx, mu, sg, epw, partH);
    reduce_h<<<3, 256>>>(partH, bmu, bsg, epb, h);
    sweep2_out<<<1, 256>>>(ctx, h, mu, sg, epw, bmu, bsg, epb, out);
}